// round 4
// baseline (speedup 1.0000x reference)
#include <cuda_runtime.h>

// SoftDTW forward, B=128, N=M=512, gamma=1.
// S = exp(-R):  S[i][j] = exp(-D[i][j]) * (S[i-1][j-1] + S[i-1][j] + S[i][j-1])
// Final: R = -(ln S + Es*ln2), with warp-uniform power-of-2 rescaling (Es ledger).
//
// One CTA per batch, 4 warps:
//   warps 0-2: producers — stream D, compute exp(-D), stage into a 44-slot smem ring,
//              diagonal placement: chunk (row r, consumer-lane l) -> slot (r+l) % 44.
//   warp 3:    consumer — wavefront DP, lane l owns cols [16l,16l+16); at step s lane l
//              processes row i = s-l. All lanes read ONE slot (s % 44) per step.
//              Neighbor passing: one shfl_up per step. No barriers in the step loop.
// Phases of 6 steps/rows; one __syncthreads per phase orders producer->consumer.

namespace {
constexpr int BATCH   = 128;
constexpr int NR      = 512;
constexpr int MC      = 512;
constexpr int KP      = 6;                      // steps/rows per phase
constexpr int RS      = 44;                     // ring slots
constexpr int LSTRIDE = 36;                     // words per lane chunk (144B): conflict-free, 16B-aligned
constexpr int SLOTW   = 32 * LSTRIDE;           // 1152 words per slot
constexpr int SMEM_BYTES = RS * SLOTW * 4;      // 202752 B
constexpr int STEPS   = NR + 31;                // 543
constexpr int NPHASE  = (STEPS + KP - 1) / KP;  // 91
constexpr unsigned FULL = 0xffffffffu;
}

__device__ __forceinline__ float4 exp4neg(float4 v) {
    float4 r;
    r.x = __expf(-v.x); r.y = __expf(-v.y);
    r.z = __expf(-v.z); r.w = __expf(-v.w);
    return r;
}

__global__ __launch_bounds__(128, 1)
void softdtw_fwd(const float* __restrict__ D, float* __restrict__ out) {
    extern __shared__ float sm[];
    const int b   = blockIdx.x;
    const int tid = threadIdx.x;
    const int w   = tid >> 5;
    const int l   = tid & 31;
    const float* __restrict__ G = D + (size_t)b * NR * MC + l * 16;

    if (w < 3) {
        // ---------------- producers (warps 0,1,2) ----------------
        float* lane_base = sm + l * LSTRIDE;

        auto load_row = [&](int r, float4 a[4]) {
            const float4* src = (const float4*)(G + (size_t)r * MC);
            a[0] = src[0]; a[1] = src[1]; a[2] = src[2]; a[3] = src[3];
        };
        auto store_row = [&](int r, const float4 a[4]) {
            float4* dst = (float4*)(lane_base + ((r + l) % RS) * SLOTW);
            dst[0] = exp4neg(a[0]); dst[1] = exp4neg(a[1]);
            dst[2] = exp4neg(a[2]); dst[3] = exp4neg(a[3]);
        };

        float4 A[4], Bv[4];
        // block 0 (rows 0..5) written directly before the loop
        {
            float4 t0[4];
            int r0 = 2 * w;
            load_row(r0, t0);     store_row(r0, t0);
            load_row(r0 + 1, t0); store_row(r0 + 1, t0);
        }
        // prefetch block 1
        { int r0 = KP + 2 * w; load_row(r0, A); load_row(r0 + 1, Bv); }

        for (int t = 0; t < NPHASE; ++t) {
            __syncthreads();
            // write block t+1 (prefetched last phase)
            const int r0 = KP * (t + 1) + 2 * w;   // r0 even -> r0+1 valid iff r0 valid
            if (r0 < NR) { store_row(r0, A); store_row(r0 + 1, Bv); }
            // prefetch block t+2
            const int r2 = r0 + KP;
            if (r2 < NR) { load_row(r2, A); load_row(r2 + 1, Bv); }
        }
    } else {
        // ---------------- consumer (warp 3) ----------------
        float h[16];
        #pragma unroll
        for (int j = 0; j < 16; ++j) h[j] = 0.f;
        float xd = (l == 0) ? 1.f : 0.f;   // diag carry; corner S[-1][-1] = 1
        int   Es = 0;
        int   slot = 0;
        const float* lane_base = sm + l * LSTRIDE;

        for (int t = 0; t < NPHASE; ++t) {
            __syncthreads();
            #pragma unroll
            for (int q = 0; q < KP; ++q) {
                const int s = t * KP + q;
                if (s < STEPS) {
                    const float4* eb = (const float4*)(lane_base + slot * SLOTW);
                    const float4 E0 = eb[0], E1 = eb[1], E2 = eb[2], E3 = eb[3];
                    float e[16] = { E0.x, E0.y, E0.z, E0.w,
                                    E1.x, E1.y, E1.z, E1.w,
                                    E2.x, E2.y, E2.z, E2.w,
                                    E3.x, E3.y, E3.z, E3.w };

                    // left neighbor: lane l-1's col-(16l-1) value at row i (its step s-1)
                    const float x  = __shfl_up_sync(FULL, h[15], 1);
                    const float xl = (l == 0) ? 0.f : x;
                    const bool  act = (unsigned)(s - l) < (unsigned)NR;

                    float p[16];
                    p[0] = e[0] * (xd + h[0]);
                    #pragma unroll
                    for (int j = 1; j < 16; ++j) p[j] = e[j] * (h[j - 1] + h[j]);

                    float c = xl;
                    #pragma unroll
                    for (int j = 0; j < 16; ++j) {
                        c = fmaf(e[j], c, p[j]);
                        h[j] = act ? c : h[j];     // freeze h outside [start,end]
                    }
                    xd = xl;                        // this step's left = next step's diag
                    slot = (slot + 1 == RS) ? 0 : slot + 1;

                    // warp-uniform power-of-2 rescale every 32 steps
                    if ((s & 31) == 31) {
                        float m = h[0];
                        #pragma unroll
                        for (int j = 1; j < 16; ++j) m = fmaxf(m, h[j]);
                        #pragma unroll
                        for (int o = 16; o; o >>= 1)
                            m = fmaxf(m, __shfl_xor_sync(FULL, m, o));
                        if (m > 0.f) {
                            const int   k = (__float_as_int(m) >> 23) - 127;
                            const float f = __int_as_float((127 - k) << 23);
                            #pragma unroll
                            for (int j = 0; j < 16; ++j) h[j] *= f;
                            xd *= f;
                            Es += k;
                        }
                    }
                }
            }
        }
        // cell (511,511) computed by lane 31 at step 542 -> h[15]
        if (l == 31)
            out[b] = -(logf(h[15]) + (float)Es * 0.69314718055994531f);
    }
}

extern "C" void kernel_launch(void* const* d_in, const int* in_sizes, int n_in,
                              void* d_out, int out_size) {
    (void)in_sizes; (void)n_in; (void)out_size;
    const float* D = (const float*)d_in[0];
    float* o       = (float*)d_out;
    cudaFuncSetAttribute(softdtw_fwd, cudaFuncAttributeMaxDynamicSharedMemorySize, SMEM_BYTES);
    softdtw_fwd<<<BATCH, 128, SMEM_BYTES>>>(D, o);
}

// round 5
// speedup vs baseline: 1.0004x; 1.0004x over previous
#include <cuda_runtime.h>

// SoftDTW forward, B=128, N=M=512, gamma=1.
// S = exp(-R):  S[i][j] = exp(-D[i][j]) * (S[i-1][j-1] + S[i-1][j] + S[i][j-1])
// Final: R = -(ln S + Es*ln2), with warp-uniform power-of-2 rescaling (Es ledger).
//
// One CTA per batch, 4 warps:
//   warps 0-2: producers — stream D, compute exp(-D), stage into a 44-slot smem ring,
//              diagonal placement: chunk (row r, consumer-lane l) -> slot (r+l) % 44.
//   warp 3:    consumer — wavefront DP, lane l owns cols [16l,16l+16); at step s lane l
//              processes row i = s-l. All lanes read ONE slot (s % 44) per step.
//              Neighbor passing: one shfl_up per step. No barriers in the step loop.
// Phases of 6 steps/rows; one __syncthreads per phase orders producer->consumer.

namespace {
constexpr int BATCH   = 128;
constexpr int NR      = 512;
constexpr int MC      = 512;
constexpr int KP      = 6;                      // steps/rows per phase
constexpr int RS      = 44;                     // ring slots
constexpr int LSTRIDE = 36;                     // words per lane chunk (144B): conflict-free, 16B-aligned
constexpr int SLOTW   = 32 * LSTRIDE;           // 1152 words per slot
constexpr int SMEM_BYTES = RS * SLOTW * 4;      // 202752 B
constexpr int STEPS   = NR + 31;                // 543
constexpr int NPHASE  = (STEPS + KP - 1) / KP;  // 91
constexpr unsigned FULL = 0xffffffffu;
}

__device__ __forceinline__ float4 exp4neg(float4 v) {
    float4 r;
    r.x = __expf(-v.x); r.y = __expf(-v.y);
    r.z = __expf(-v.z); r.w = __expf(-v.w);
    return r;
}

__global__ __launch_bounds__(128, 1)
void softdtw_fwd(const float* __restrict__ D, float* __restrict__ out) {
    extern __shared__ float sm[];
    const int b   = blockIdx.x;
    const int tid = threadIdx.x;
    const int w   = tid >> 5;
    const int l   = tid & 31;
    const float* __restrict__ G = D + (size_t)b * NR * MC + l * 16;

    if (w < 3) {
        // ---------------- producers (warps 0,1,2) ----------------
        float* lane_base = sm + l * LSTRIDE;

        auto load_row = [&](int r, float4 a[4]) {
            const float4* src = (const float4*)(G + (size_t)r * MC);
            a[0] = src[0]; a[1] = src[1]; a[2] = src[2]; a[3] = src[3];
        };
        auto store_row = [&](int r, const float4 a[4]) {
            float4* dst = (float4*)(lane_base + ((r + l) % RS) * SLOTW);
            dst[0] = exp4neg(a[0]); dst[1] = exp4neg(a[1]);
            dst[2] = exp4neg(a[2]); dst[3] = exp4neg(a[3]);
        };

        float4 A[4], Bv[4];
        // block 0 (rows 0..5) written directly before the loop
        {
            float4 t0[4];
            int r0 = 2 * w;
            load_row(r0, t0);     store_row(r0, t0);
            load_row(r0 + 1, t0); store_row(r0 + 1, t0);
        }
        // prefetch block 1
        { int r0 = KP + 2 * w; load_row(r0, A); load_row(r0 + 1, Bv); }

        for (int t = 0; t < NPHASE; ++t) {
            __syncthreads();
            // write block t+1 (prefetched last phase)
            const int r0 = KP * (t + 1) + 2 * w;   // r0 even -> r0+1 valid iff r0 valid
            if (r0 < NR) { store_row(r0, A); store_row(r0 + 1, Bv); }
            // prefetch block t+2
            const int r2 = r0 + KP;
            if (r2 < NR) { load_row(r2, A); load_row(r2 + 1, Bv); }
        }
    } else {
        // ---------------- consumer (warp 3) ----------------
        float h[16];
        #pragma unroll
        for (int j = 0; j < 16; ++j) h[j] = 0.f;
        float xd = (l == 0) ? 1.f : 0.f;   // diag carry; corner S[-1][-1] = 1
        int   Es = 0;
        int   slot = 0;
        const float* lane_base = sm + l * LSTRIDE;

        for (int t = 0; t < NPHASE; ++t) {
            __syncthreads();
            #pragma unroll
            for (int q = 0; q < KP; ++q) {
                const int s = t * KP + q;
                if (s < STEPS) {
                    const float4* eb = (const float4*)(lane_base + slot * SLOTW);
                    const float4 E0 = eb[0], E1 = eb[1], E2 = eb[2], E3 = eb[3];
                    float e[16] = { E0.x, E0.y, E0.z, E0.w,
                                    E1.x, E1.y, E1.z, E1.w,
                                    E2.x, E2.y, E2.z, E2.w,
                                    E3.x, E3.y, E3.z, E3.w };

                    // left neighbor: lane l-1's col-(16l-1) value at row i (its step s-1)
                    const float x  = __shfl_up_sync(FULL, h[15], 1);
                    const float xl = (l == 0) ? 0.f : x;
                    const bool  act = (unsigned)(s - l) < (unsigned)NR;

                    float p[16];
                    p[0] = e[0] * (xd + h[0]);
                    #pragma unroll
                    for (int j = 1; j < 16; ++j) p[j] = e[j] * (h[j - 1] + h[j]);

                    float c = xl;
                    #pragma unroll
                    for (int j = 0; j < 16; ++j) {
                        c = fmaf(e[j], c, p[j]);
                        h[j] = act ? c : h[j];     // freeze h outside [start,end]
                    }
                    xd = xl;                        // this step's left = next step's diag
                    slot = (slot + 1 == RS) ? 0 : slot + 1;

                    // warp-uniform power-of-2 rescale every 32 steps
                    if ((s & 31) == 31) {
                        float m = h[0];
                        #pragma unroll
                        for (int j = 1; j < 16; ++j) m = fmaxf(m, h[j]);
                        #pragma unroll
                        for (int o = 16; o; o >>= 1)
                            m = fmaxf(m, __shfl_xor_sync(FULL, m, o));
                        if (m > 0.f) {
                            const int   k = (__float_as_int(m) >> 23) - 127;
                            const float f = __int_as_float((127 - k) << 23);
                            #pragma unroll
                            for (int j = 0; j < 16; ++j) h[j] *= f;
                            xd *= f;
                            Es += k;
                        }
                    }
                }
            }
        }
        // cell (511,511) computed by lane 31 at step 542 -> h[15]
        if (l == 31)
            out[b] = -(logf(h[15]) + (float)Es * 0.69314718055994531f);
    }
}

extern "C" void kernel_launch(void* const* d_in, const int* in_sizes, int n_in,
                              void* d_out, int out_size) {
    (void)in_sizes; (void)n_in; (void)out_size;
    const float* D = (const float*)d_in[0];
    float* o       = (float*)d_out;
    cudaFuncSetAttribute(softdtw_fwd, cudaFuncAttributeMaxDynamicSharedMemorySize, SMEM_BYTES);
    softdtw_fwd<<<BATCH, 128, SMEM_BYTES>>>(D, o);
}